// round 3
// baseline (speedup 1.0000x reference)
#include <cuda_runtime.h>
#include <cuda_bf16.h>
#include <math.h>
#include <stdint.h>

#define BATCH 4
#define SEQ 1024
#define DMODEL 768
#define NHEAD 12
#define DHEAD 64
#define BN (BATCH*SEQ)

// ---- scratch (static device globals; no allocation) ----
__device__ float g_q[BN * DMODEL];
__device__ float g_k[BN * DMODEL];
__device__ float g_v[BN * DMODEL];
__device__ float g_attn[(size_t)BATCH * NHEAD * SEQ * SEQ];  // 192 MB

// ============================================================
// MMA helpers (m16n8k16 bf16, fp32 accum) + ldmatrix
// ============================================================
__device__ __forceinline__ uint32_t smem_u32(const void* p) {
    return (uint32_t)__cvta_generic_to_shared(p);
}

__device__ __forceinline__ void ldsm4(uint32_t addr, uint32_t* r) {
    asm volatile("ldmatrix.sync.aligned.m8n8.x4.shared.b16 {%0,%1,%2,%3}, [%4];\n"
                 : "=r"(r[0]), "=r"(r[1]), "=r"(r[2]), "=r"(r[3])
                 : "r"(addr));
}

__device__ __forceinline__ void mma_bf16(float* c, const uint32_t* a, const uint32_t* b) {
    asm volatile(
        "mma.sync.aligned.m16n8k16.row.col.f32.bf16.bf16.f32 "
        "{%0,%1,%2,%3}, {%4,%5,%6,%7}, {%8,%9}, {%0,%1,%2,%3};\n"
        : "+f"(c[0]), "+f"(c[1]), "+f"(c[2]), "+f"(c[3])
        : "r"(a[0]), "r"(a[1]), "r"(a[2]), "r"(a[3]), "r"(b[0]), "r"(b[1]));
}

__device__ __forceinline__ void split2(float v, __nv_bfloat16& h, __nv_bfloat16& l) {
    h = __float2bfloat16(v);
    l = __float2bfloat16(v - __bfloat162float(h));
}

// A fragments: MT m16-tiles, row-major smem [m][k]
template <int PITCH, int MT>
__device__ __forceinline__ void ldA(const __nv_bfloat16* P, int arow, int acol,
                                    uint32_t a[][4]) {
#pragma unroll
    for (int mt = 0; mt < MT; mt++)
        ldsm4(smem_u32(P + (arow + mt * 16) * PITCH + acol), a[mt]);
}

// B fragments: NP pairs of n8-tiles, smem [n][k]
template <int PITCH, int NP>
__device__ __forceinline__ void ldB(const __nv_bfloat16* P, int brow, int bcol,
                                    uint32_t b[][2]) {
#pragma unroll
    for (int p = 0; p < NP; p++) {
        uint32_t r[4];
        ldsm4(smem_u32(P + (brow + p * 16) * PITCH + bcol), r);
        b[2 * p][0] = r[0];
        b[2 * p][1] = r[1];
        b[2 * p + 1][0] = r[2];
        b[2 * p + 1][1] = r[3];
    }
}

template <int MT, int NT>
__device__ __forceinline__ void mma_tiles(float (*acc)[NT][4], uint32_t a[][4],
                                          uint32_t b[][2]) {
#pragma unroll
    for (int mt = 0; mt < MT; mt++)
#pragma unroll
        for (int nt = 0; nt < NT; nt++) mma_bf16(acc[mt][nt], a[mt], b[nt]);
}

// ============================================================
// Kernel 1: QKV projections. C = X*W. CTA 128x128, BK=32,
// 256 thr (8 warps, warp 64x32). bf16-split HMMA.
// ============================================================
#define P1 40  // k-pitch for BK=32 tiles (80B rows: conflict-free LDSM)

__global__ __launch_bounds__(256) void qkv_gemm_kernel(
    const float* __restrict__ x, const float* __restrict__ Wq,
    const float* __restrict__ Wk, const float* __restrict__ Wv) {
    const int z = blockIdx.z;
    const float* __restrict__ W = (z == 0) ? Wq : (z == 1) ? Wk : Wv;
    float* __restrict__ C = (z == 0) ? g_q : (z == 1) ? g_k : g_v;
    const float scale = (z == 0) ? 0.125f : 1.0f;

    const int m0 = blockIdx.y * 128;
    const int n0 = blockIdx.x * 128;

    __shared__ __align__(16) __nv_bfloat16 Xh[128 * P1], Xl[128 * P1];
    __shared__ __align__(16) __nv_bfloat16 Wh[128 * P1], Wl[128 * P1];

    const int t = threadIdx.x, lane = t & 31, w = t >> 5;
    const int wm = (w & 1) * 64, wn = (w >> 1) * 32;

    float acc[4][4][4] = {};

    const int arow = wm + (lane & 15);
    const int bro = wn + (lane & 7) + (lane >> 4) * 8;

    for (int kk = 0; kk < DMODEL; kk += 32) {
        // X tile [128 m][32 k] -> split planes
#pragma unroll
        for (int i = 0; i < 4; i++) {
            int idx = t + i * 256;
            int r = idx >> 3, c = (idx & 7) * 4;
            float4 v4 = *(const float4*)(x + (size_t)(m0 + r) * DMODEL + kk + c);
            int o = r * P1 + c;
            split2(v4.x, Xh[o], Xl[o]);
            split2(v4.y, Xh[o + 1], Xl[o + 1]);
            split2(v4.z, Xh[o + 2], Xl[o + 2]);
            split2(v4.w, Xh[o + 3], Xl[o + 3]);
        }
        // W tile [32 k][128 n] -> transposed split planes [n][k]
#pragma unroll
        for (int i = 0; i < 4; i++) {
            int idx = t + i * 256;
            int kr = idx >> 5, n = (idx & 31) * 4;
            float4 v4 = *(const float4*)(W + (size_t)(kk + kr) * DMODEL + n0 + n);
            split2(v4.x, Wh[n * P1 + kr], Wl[n * P1 + kr]);
            split2(v4.y, Wh[(n + 1) * P1 + kr], Wl[(n + 1) * P1 + kr]);
            split2(v4.z, Wh[(n + 2) * P1 + kr], Wl[(n + 2) * P1 + kr]);
            split2(v4.w, Wh[(n + 3) * P1 + kr], Wl[(n + 3) * P1 + kr]);
        }
        __syncthreads();

#pragma unroll
        for (int ks = 0; ks < 2; ks++) {
            const int acol = ks * 16 + (lane >> 4) * 8;
            const int bcol = ks * 16 + ((lane >> 3) & 1) * 8;
            uint32_t a[4][4], b[4][2];
            ldA<P1, 4>(Xh, arow, acol, a);
            ldB<P1, 2>(Wh, bro, bcol, b);
            mma_tiles<4, 4>(acc, a, b);  // hi*hi
            ldB<P1, 2>(Wl, bro, bcol, b);
            mma_tiles<4, 4>(acc, a, b);  // hi*lo
            ldA<P1, 4>(Xl, arow, acol, a);
            ldB<P1, 2>(Wh, bro, bcol, b);
            mma_tiles<4, 4>(acc, a, b);  // lo*hi
        }
        __syncthreads();
    }

    const int g = lane >> 2, tig = lane & 3;
#pragma unroll
    for (int mt = 0; mt < 4; mt++) {
        int row = m0 + wm + mt * 16 + g;
#pragma unroll
        for (int nt = 0; nt < 4; nt++) {
            int col = n0 + wn + nt * 8 + 2 * tig;
            *(float2*)(C + (size_t)row * DMODEL + col) =
                make_float2(acc[mt][nt][0] * scale, acc[mt][nt][1] * scale);
            *(float2*)(C + (size_t)(row + 8) * DMODEL + col) =
                make_float2(acc[mt][nt][2] * scale, acc[mt][nt][3] * scale);
        }
    }
}

// ============================================================
// Kernel 2: S[b,h,i,j] = sum_d q[i,d]*k[j,d]. CTA 128x128,
// K=64 resident. 256 thr, warp 64x32. bf16-split HMMA.
// ============================================================
#define P2 72  // k-pitch for K=64 (144B rows: conflict-free LDSM)

__global__ __launch_bounds__(256) void scores_kernel() {
    extern __shared__ __nv_bfloat16 sm2[];
    __nv_bfloat16* Qh = sm2;
    __nv_bfloat16* Ql = Qh + 128 * P2;
    __nv_bfloat16* Kh = Ql + 128 * P2;
    __nv_bfloat16* Kl = Kh + 128 * P2;

    const int bh = blockIdx.z;
    const int b = bh / NHEAD, h = bh % NHEAD;
    const int i0 = blockIdx.y * 128;
    const int j0 = blockIdx.x * 128;

    const int t = threadIdx.x, lane = t & 31, w = t >> 5;
    const int wm = (w & 1) * 64, wn = (w >> 1) * 32;

    const float* qb = g_q + (size_t)b * SEQ * DMODEL + h * DHEAD;
    const float* kb = g_k + (size_t)b * SEQ * DMODEL + h * DHEAD;

#pragma unroll
    for (int i = 0; i < 8; i++) {
        int idx = t + i * 256;
        int r = idx >> 4, c = (idx & 15) * 4;
        float4 v4 = *(const float4*)(qb + (size_t)(i0 + r) * DMODEL + c);
        int o = r * P2 + c;
        split2(v4.x, Qh[o], Ql[o]);
        split2(v4.y, Qh[o + 1], Ql[o + 1]);
        split2(v4.z, Qh[o + 2], Ql[o + 2]);
        split2(v4.w, Qh[o + 3], Ql[o + 3]);
        v4 = *(const float4*)(kb + (size_t)(j0 + r) * DMODEL + c);
        split2(v4.x, Kh[o], Kl[o]);
        split2(v4.y, Kh[o + 1], Kl[o + 1]);
        split2(v4.z, Kh[o + 2], Kl[o + 2]);
        split2(v4.w, Kh[o + 3], Kl[o + 3]);
    }
    __syncthreads();

    float acc[4][4][4] = {};
    const int arow = wm + (lane & 15);
    const int bro = wn + (lane & 7) + (lane >> 4) * 8;

#pragma unroll
    for (int ks = 0; ks < 4; ks++) {
        const int acol = ks * 16 + (lane >> 4) * 8;
        const int bcol = ks * 16 + ((lane >> 3) & 1) * 8;
        uint32_t a[4][4], b[4][2];
        ldA<P2, 4>(Qh, arow, acol, a);
        ldB<P2, 2>(Kh, bro, bcol, b);
        mma_tiles<4, 4>(acc, a, b);
        ldB<P2, 2>(Kl, bro, bcol, b);
        mma_tiles<4, 4>(acc, a, b);
        ldA<P2, 4>(Ql, arow, acol, a);
        ldB<P2, 2>(Kh, bro, bcol, b);
        mma_tiles<4, 4>(acc, a, b);
    }

    float* Sb = g_attn + (size_t)(b * NHEAD + h) * SEQ * SEQ;
    const int g = lane >> 2, tig = lane & 3;
#pragma unroll
    for (int mt = 0; mt < 4; mt++) {
        int row = i0 + wm + mt * 16 + g;
#pragma unroll
        for (int nt = 0; nt < 4; nt++) {
            int col = j0 + wn + nt * 8 + 2 * tig;
            *(float2*)(Sb + (size_t)row * SEQ + col) =
                make_float2(acc[mt][nt][0], acc[mt][nt][1]);
            *(float2*)(Sb + (size_t)(row + 8) * SEQ + col) =
                make_float2(acc[mt][nt][2], acc[mt][nt][3]);
        }
    }
}

// ============================================================
// Kernel 3: per (b,q): softmax(k) per head, theta head-mix,
// LayerNorm(k). 512 thr per CTA, register-resident. (unchanged)
// ============================================================
#define NW3 16

__device__ __forceinline__ void blockReduceMax12(float v[12], float* red) {
#pragma unroll
    for (int h = 0; h < 12; h++)
#pragma unroll
        for (int o = 16; o; o >>= 1)
            v[h] = fmaxf(v[h], __shfl_xor_sync(0xffffffffu, v[h], o));
    int w = threadIdx.x >> 5;
    if ((threadIdx.x & 31) == 0) {
#pragma unroll
        for (int h = 0; h < 12; h++) red[h * NW3 + w] = v[h];
    }
    __syncthreads();
#pragma unroll
    for (int h = 0; h < 12; h++) {
        float m = red[h * NW3];
#pragma unroll
        for (int w2 = 1; w2 < NW3; w2++) m = fmaxf(m, red[h * NW3 + w2]);
        v[h] = m;
    }
    __syncthreads();
}

__device__ __forceinline__ void blockReduceSum12(float v[12], float* red) {
#pragma unroll
    for (int h = 0; h < 12; h++)
#pragma unroll
        for (int o = 16; o; o >>= 1)
            v[h] += __shfl_xor_sync(0xffffffffu, v[h], o);
    int w = threadIdx.x >> 5;
    if ((threadIdx.x & 31) == 0) {
#pragma unroll
        for (int h = 0; h < 12; h++) red[h * NW3 + w] = v[h];
    }
    __syncthreads();
#pragma unroll
    for (int h = 0; h < 12; h++) {
        float m = red[h * NW3];
#pragma unroll
        for (int w2 = 1; w2 < NW3; w2++) m += red[h * NW3 + w2];
        v[h] = m;
    }
    __syncthreads();
}

__device__ __forceinline__ void blockReduceSum24(float v[24], float* red) {
#pragma unroll
    for (int h = 0; h < 24; h++)
#pragma unroll
        for (int o = 16; o; o >>= 1)
            v[h] += __shfl_xor_sync(0xffffffffu, v[h], o);
    int w = threadIdx.x >> 5;
    if ((threadIdx.x & 31) == 0) {
#pragma unroll
        for (int h = 0; h < 24; h++) red[h * NW3 + w] = v[h];
    }
    __syncthreads();
#pragma unroll
    for (int h = 0; h < 24; h++) {
        float m = red[h * NW3];
#pragma unroll
        for (int w2 = 1; w2 < NW3; w2++) m += red[h * NW3 + w2];
        v[h] = m;
    }
    __syncthreads();
}

__global__ __launch_bounds__(512) void softmax_theta_ln_kernel(
    const float* __restrict__ theta,
    const float* __restrict__ lnS,
    const float* __restrict__ lnB) {
    __shared__ float th[144];
    __shared__ float red[24 * NW3];

    const int bq = blockIdx.x;
    const int b = bq >> 10;
    const int qi = bq & 1023;
    const int t = threadIdx.x;

    if (t < 144) th[t] = theta[t];

    float2 r[NHEAD];
#pragma unroll
    for (int h = 0; h < NHEAD; h++) {
        const float* src = g_attn + ((size_t)(b * NHEAD + h) * SEQ + qi) * SEQ;
        r[h] = *(const float2*)(src + 2 * t);
    }
    float2 s2v = *(const float2*)(lnS + 2 * t);
    float2 b2v = *(const float2*)(lnB + 2 * t);
    __syncthreads();

    float mx[NHEAD];
#pragma unroll
    for (int h = 0; h < NHEAD; h++) mx[h] = fmaxf(r[h].x, r[h].y);
    blockReduceMax12(mx, red);

    float sum[NHEAD];
#pragma unroll
    for (int h = 0; h < NHEAD; h++) {
        r[h].x = __expf(r[h].x - mx[h]);
        r[h].y = __expf(r[h].y - mx[h]);
        sum[h] = r[h].x + r[h].y;
    }
    blockReduceSum12(sum, red);
#pragma unroll
    for (int h = 0; h < NHEAD; h++) {
        float inv = 1.0f / sum[h];
        r[h].x *= inv;
        r[h].y *= inv;
    }

    float2 a[NHEAD];
#pragma unroll
    for (int i = 0; i < NHEAD; i++) {
        float ax = 0.f, ay = 0.f;
#pragma unroll
        for (int h = 0; h < NHEAD; h++) {
            float wv = th[h * NHEAD + i];
            ax += wv * r[h].x;
            ay += wv * r[h].y;
        }
        a[i].x = ax;
        a[i].y = ay;
    }

    float st[24];
#pragma unroll
    for (int i = 0; i < NHEAD; i++) {
        st[i] = a[i].x + a[i].y;
        st[12 + i] = a[i].x * a[i].x + a[i].y * a[i].y;
    }
    blockReduceSum24(st, red);

#pragma unroll
    for (int i = 0; i < NHEAD; i++) {
        float mean = st[i] * (1.0f / SEQ);
        float var = st[12 + i] * (1.0f / SEQ) - mean * mean;
        float rstd = rsqrtf(var + 1e-6f);
        float* dst = g_attn + ((size_t)(b * NHEAD + i) * SEQ + qi) * SEQ;
        float2 o;
        o.x = (a[i].x - mean) * rstd * s2v.x + b2v.x;
        o.y = (a[i].y - mean) * rstd * s2v.y + b2v.y;
        *(float2*)(dst + 2 * t) = o;
    }
}

// ============================================================
// Kernel 4: out[b,k,h,d] = sum_q A[b,h,q,k]*v[b,q,h,d]
// = A^T V per (b,h). CTA: 128(k) x 64(d), q-chunk 32.
// 256 thr, warp 32x32. A,V transposed into smem at load.
// ============================================================
#define P4 40

__global__ __launch_bounds__(256) void out_gemm_kernel(float* __restrict__ out) {
    const int bh = blockIdx.y;
    const int b = bh / NHEAD, h = bh % NHEAD;
    const int k0b = blockIdx.x * 128;

    __shared__ __align__(16) __nv_bfloat16 Ah[128 * P4], Al[128 * P4];  // [k][q]
    __shared__ __align__(16) __nv_bfloat16 Vh[64 * P4], Vl[64 * P4];    // [d][q]

    const int t = threadIdx.x, lane = t & 31, w = t >> 5;
    const int wm = (w & 3) * 32;   // k-dim
    const int wn = (w >> 2) * 32;  // d-dim

    const float* Ab = g_attn + (size_t)(b * NHEAD + h) * SEQ * SEQ;
    const float* vb = g_v + (size_t)b * SEQ * DMODEL + h * DHEAD;

    float acc[2][4][4] = {};
    const int arow = wm + (lane & 15);
    const int bro = wn + (lane & 7) + (lane >> 4) * 8;

    for (int q0 = 0; q0 < SEQ; q0 += 32) {
        // attn tile [32 q][128 k] -> transposed split planes [k][q]
#pragma unroll
        for (int i = 0; i < 4; i++) {
            int idx = t + i * 256;
            int r = idx >> 5, k = (idx & 31) * 4;
            float4 v4 = *(const float4*)(Ab + (size_t)(q0 + r) * SEQ + k0b + k);
            split2(v4.x, Ah[k * P4 + r], Al[k * P4 + r]);
            split2(v4.y, Ah[(k + 1) * P4 + r], Al[(k + 1) * P4 + r]);
            split2(v4.z, Ah[(k + 2) * P4 + r], Al[(k + 2) * P4 + r]);
            split2(v4.w, Ah[(k + 3) * P4 + r], Al[(k + 3) * P4 + r]);
        }
        // v tile [32 q][64 d] -> transposed split planes [d][q]
#pragma unroll
        for (int i = 0; i < 2; i++) {
            int idx = t + i * 256;
            int r = idx >> 4, d = (idx & 15) * 4;
            float4 v4 = *(const float4*)(vb + (size_t)(q0 + r) * DMODEL + d);
            split2(v4.x, Vh[d * P4 + r], Vl[d * P4 + r]);
            split2(v4.y, Vh[(d + 1) * P4 + r], Vl[(d + 1) * P4 + r]);
            split2(v4.z, Vh[(d + 2) * P4 + r], Vl[(d + 2) * P4 + r]);
            split2(v4.w, Vh[(d + 3) * P4 + r], Vl[(d + 3) * P4 + r]);
        }
        __syncthreads();

#pragma unroll
        for (int ks = 0; ks < 2; ks++) {
            const int acol = ks * 16 + (lane >> 4) * 8;
            const int bcol = ks * 16 + ((lane >> 3) & 1) * 8;
            uint32_t a[2][4], bfr[4][2];
            ldA<P4, 2>(Ah, arow, acol, a);
            ldB<P4, 2>(Vh, bro, bcol, bfr);
            mma_tiles<2, 4>(acc, a, bfr);
            ldB<P4, 2>(Vl, bro, bcol, bfr);
            mma_tiles<2, 4>(acc, a, bfr);
            ldA<P4, 2>(Al, arow, acol, a);
            ldB<P4, 2>(Vh, bro, bcol, bfr);
            mma_tiles<2, 4>(acc, a, bfr);
        }
        __syncthreads();
    }

    const int g = lane >> 2, tig = lane & 3;
#pragma unroll
    for (int mt = 0; mt < 2; mt++) {
        int row = k0b + wm + mt * 16 + g;
#pragma unroll
        for (int nt = 0; nt < 4; nt++) {
            int col = h * DHEAD + wn + nt * 8 + 2 * tig;
            *(float2*)(out + (size_t)(b * SEQ + row) * DMODEL + col) =
                make_float2(acc[mt][nt][0], acc[mt][nt][1]);
            *(float2*)(out + (size_t)(b * SEQ + row + 8) * DMODEL + col) =
                make_float2(acc[mt][nt][2], acc[mt][nt][3]);
        }
    }
}

// ============================================================
extern "C" void kernel_launch(void* const* d_in, const int* in_sizes, int n_in,
                              void* d_out, int out_size) {
    const float* x     = (const float*)d_in[0];
    const float* Wq    = (const float*)d_in[1];
    const float* Wk    = (const float*)d_in[2];
    const float* Wv    = (const float*)d_in[3];
    const float* theta = (const float*)d_in[4];
    const float* lnS   = (const float*)d_in[5];
    const float* lnB   = (const float*)d_in[6];
    float* out = (float*)d_out;

    // 1. QKV projections (bf16-split HMMA)
    {
        dim3 grid(DMODEL / 128, BN / 128, 3);
        qkv_gemm_kernel<<<grid, 256>>>(x, Wq, Wk, Wv);
    }
    // 2. attention scores (bf16-split HMMA)
    {
        int smem = 4 * 128 * P2 * sizeof(__nv_bfloat16);  // 73728 B
        cudaFuncSetAttribute(scores_kernel,
                             cudaFuncAttributeMaxDynamicSharedMemorySize, smem);
        dim3 grid(SEQ / 128, SEQ / 128, BATCH * NHEAD);
        scores_kernel<<<grid, 256, smem>>>();
    }
    // 3. fused softmax + theta mix + LayerNorm
    {
        softmax_theta_ln_kernel<<<BATCH * SEQ, 512>>>(theta, lnS, lnB);
    }
    // 4. output GEMM (A^T V, bf16-split HMMA)
    {
        dim3 grid(SEQ / 128, BATCH * NHEAD);
        out_gemm_kernel<<<grid, 256>>>(out);
    }
}

// round 4
// speedup vs baseline: 1.6430x; 1.6430x over previous
#include <cuda_runtime.h>
#include <cuda_bf16.h>
#include <math.h>
#include <stdint.h>

#define BATCH 4
#define SEQ 1024
#define DMODEL 768
#define NHEAD 12
#define DHEAD 64
#define BN (BATCH*SEQ)

// ---- scratch (static device globals; no allocation) ----
__device__ float g_attn[(size_t)BATCH * NHEAD * SEQ * SEQ];        // 192 MB fp32
__device__ __nv_bfloat16 g_ah[(size_t)BATCH * NHEAD * SEQ * SEQ];  // 96 MB
__device__ __nv_bfloat16 g_al[(size_t)BATCH * NHEAD * SEQ * SEQ];  // 96 MB
__device__ __nv_bfloat16 g_qh[BN * DMODEL], g_ql[BN * DMODEL];
__device__ __nv_bfloat16 g_kh[BN * DMODEL], g_kl[BN * DMODEL];
__device__ __nv_bfloat16 g_vh[BN * DMODEL], g_vl[BN * DMODEL];

// ============================================================
// helpers
// ============================================================
__device__ __forceinline__ uint32_t smem_u32(const void* p) {
    return (uint32_t)__cvta_generic_to_shared(p);
}

__device__ __forceinline__ void ldsm4(uint32_t addr, uint32_t* r) {
    asm volatile("ldmatrix.sync.aligned.m8n8.x4.shared.b16 {%0,%1,%2,%3}, [%4];\n"
                 : "=r"(r[0]), "=r"(r[1]), "=r"(r[2]), "=r"(r[3])
                 : "r"(addr));
}

__device__ __forceinline__ void ldsm4t(uint32_t addr, uint32_t* r) {
    asm volatile("ldmatrix.sync.aligned.m8n8.x4.trans.shared.b16 {%0,%1,%2,%3}, [%4];\n"
                 : "=r"(r[0]), "=r"(r[1]), "=r"(r[2]), "=r"(r[3])
                 : "r"(addr));
}

__device__ __forceinline__ void mma_bf16(float* c, const uint32_t* a, const uint32_t* b) {
    asm volatile(
        "mma.sync.aligned.m16n8k16.row.col.f32.bf16.bf16.f32 "
        "{%0,%1,%2,%3}, {%4,%5,%6,%7}, {%8,%9}, {%0,%1,%2,%3};\n"
        : "+f"(c[0]), "+f"(c[1]), "+f"(c[2]), "+f"(c[3])
        : "r"(a[0]), "r"(a[1]), "r"(a[2]), "r"(a[3]), "r"(b[0]), "r"(b[1]));
}

__device__ __forceinline__ void split2(float v, __nv_bfloat16& h, __nv_bfloat16& l) {
    h = __float2bfloat16(v);
    l = __float2bfloat16(v - __bfloat162float(h));
}

__device__ __forceinline__ uint32_t bpack(__nv_bfloat16 a, __nv_bfloat16 b) {
    __nv_bfloat162 p = __halves2bfloat162(a, b);
    return *reinterpret_cast<uint32_t*>(&p);
}

// split 4 consecutive floats into hi/lo planes, 8B packed stores
__device__ __forceinline__ void split_store4(float4 v, __nv_bfloat16* H,
                                             __nv_bfloat16* L) {
    __nv_bfloat16 h0, h1, h2, h3, l0, l1, l2, l3;
    split2(v.x, h0, l0);
    split2(v.y, h1, l1);
    split2(v.z, h2, l2);
    split2(v.w, h3, l3);
    *reinterpret_cast<uint2*>(H) = make_uint2(bpack(h0, h1), bpack(h2, h3));
    *reinterpret_cast<uint2*>(L) = make_uint2(bpack(l0, l1), bpack(l2, l3));
}

// A fragments, non-trans: smem [m][k], MT m16 tiles
template <int PITCH, int MT>
__device__ __forceinline__ void ldA(const __nv_bfloat16* P, int arow, int acol,
                                    uint32_t a[][4]) {
#pragma unroll
    for (int mt = 0; mt < MT; mt++)
        ldsm4(smem_u32(P + (arow + mt * 16) * PITCH + acol), a[mt]);
}

// B fragments, non-trans: smem [n][k], NP pairs of n8 tiles
template <int PITCH, int NP>
__device__ __forceinline__ void ldB(const __nv_bfloat16* P, int brow, int bcol,
                                    uint32_t b[][2]) {
#pragma unroll
    for (int p = 0; p < NP; p++) {
        uint32_t r[4];
        ldsm4(smem_u32(P + (brow + p * 16) * PITCH + bcol), r);
        b[2 * p][0] = r[0];
        b[2 * p][1] = r[1];
        b[2 * p + 1][0] = r[2];
        b[2 * p + 1][1] = r[3];
    }
}

// A fragments via trans: smem holds A^T as [K][m] (K = contraction)
template <int PITCH, int MT>
__device__ __forceinline__ void ldAT(const __nv_bfloat16* P, int kc, int m0,
                                     int lane, uint32_t a[][4]) {
    const int row = kc + (lane & 7) + ((lane >> 4) & 1) * 8;
    const int cb = ((lane >> 3) & 1) * 8;
#pragma unroll
    for (int mt = 0; mt < MT; mt++)
        ldsm4t(smem_u32(P + row * PITCH + m0 + mt * 16 + cb), a[mt]);
}

// B fragments via trans: smem holds B as [K][n] (K = contraction)
template <int PITCH, int NP>
__device__ __forceinline__ void ldBT(const __nv_bfloat16* P, int kc, int n0,
                                     int lane, uint32_t b[][2]) {
    const int row = kc + (lane & 7) + ((lane >> 3) & 1) * 8;
    const int cb = ((lane >> 4) & 1) * 8;
#pragma unroll
    for (int p = 0; p < NP; p++) {
        uint32_t r[4];
        ldsm4t(smem_u32(P + row * PITCH + n0 + p * 16 + cb), r);
        b[2 * p][0] = r[0];
        b[2 * p][1] = r[1];
        b[2 * p + 1][0] = r[2];
        b[2 * p + 1][1] = r[3];
    }
}

template <int MT, int NT>
__device__ __forceinline__ void mma_tiles(float (*acc)[NT][4], uint32_t a[][4],
                                          uint32_t b[][2]) {
#pragma unroll
    for (int mt = 0; mt < MT; mt++)
#pragma unroll
        for (int nt = 0; nt < NT; nt++) mma_bf16(acc[mt][nt], a[mt], b[nt]);
}

// ============================================================
// Kernel 1: QKV projections. 128x128 tile, BK=32, 256 thr,
// warp 64x32. Writes bf16 hi/lo planes to gmem.
// ============================================================
#define P1X 40   // [m][k] plane pitch (80B rows)
#define P1W 136  // [k][n] plane pitch (272B rows)

__global__ __launch_bounds__(256) void qkv_gemm_kernel(
    const float* __restrict__ x, const float* __restrict__ Wq,
    const float* __restrict__ Wk, const float* __restrict__ Wv) {
    const int z = blockIdx.z;
    const float* __restrict__ W = (z == 0) ? Wq : (z == 1) ? Wk : Wv;
    __nv_bfloat16* Ch = (z == 0) ? g_qh : (z == 1) ? g_kh : g_vh;
    __nv_bfloat16* Cl = (z == 0) ? g_ql : (z == 1) ? g_kl : g_vl;
    const float scale = (z == 0) ? 0.125f : 1.0f;

    const int m0 = blockIdx.y * 128;
    const int n0 = blockIdx.x * 128;

    __shared__ __align__(16) __nv_bfloat16 Xh[128 * P1X], Xl[128 * P1X];
    __shared__ __align__(16) __nv_bfloat16 Wh2[32 * P1W], Wl2[32 * P1W];

    const int t = threadIdx.x, lane = t & 31, w = t >> 5;
    const int wm = (w & 1) * 64, wn = (w >> 1) * 32;

    float acc[4][4][4] = {};
    const int arow = wm + (lane & 15);

    for (int kk = 0; kk < DMODEL; kk += 32) {
        // X tile [128 m][32 k], row-major split planes
#pragma unroll
        for (int i = 0; i < 4; i++) {
            int idx = t + i * 256;
            int r = idx >> 3, c = (idx & 7) * 4;
            float4 v4 = *(const float4*)(x + (size_t)(m0 + r) * DMODEL + kk + c);
            split_store4(v4, &Xh[r * P1X + c], &Xl[r * P1X + c]);
        }
        // W tile [32 k][128 n], row-major split planes (trans at LDSM)
#pragma unroll
        for (int i = 0; i < 4; i++) {
            int idx = t + i * 256;
            int kr = idx >> 5, n = (idx & 31) * 4;
            float4 v4 = *(const float4*)(W + (size_t)(kk + kr) * DMODEL + n0 + n);
            split_store4(v4, &Wh2[kr * P1W + n], &Wl2[kr * P1W + n]);
        }
        __syncthreads();

#pragma unroll
        for (int ks = 0; ks < 2; ks++) {
            const int acol = ks * 16 + (lane >> 4) * 8;
            uint32_t a[4][4], b[4][2];
            ldA<P1X, 4>(Xh, arow, acol, a);
            ldBT<P1W, 2>(Wh2, ks * 16, wn, lane, b);
            mma_tiles<4, 4>(acc, a, b);
            ldBT<P1W, 2>(Wl2, ks * 16, wn, lane, b);
            mma_tiles<4, 4>(acc, a, b);
            ldA<P1X, 4>(Xl, arow, acol, a);
            ldBT<P1W, 2>(Wh2, ks * 16, wn, lane, b);
            mma_tiles<4, 4>(acc, a, b);
        }
        __syncthreads();
    }

    const int g = lane >> 2, tig = lane & 3;
#pragma unroll
    for (int mt = 0; mt < 4; mt++) {
        int row = m0 + wm + mt * 16 + g;
#pragma unroll
        for (int nt = 0; nt < 4; nt++) {
            int col = n0 + wn + nt * 8 + 2 * tig;
            __nv_bfloat16 h0, l0, h1, l1;
            split2(acc[mt][nt][0] * scale, h0, l0);
            split2(acc[mt][nt][1] * scale, h1, l1);
            *(__nv_bfloat162*)(Ch + (size_t)row * DMODEL + col) = __halves2bfloat162(h0, h1);
            *(__nv_bfloat162*)(Cl + (size_t)row * DMODEL + col) = __halves2bfloat162(l0, l1);
            split2(acc[mt][nt][2] * scale, h0, l0);
            split2(acc[mt][nt][3] * scale, h1, l1);
            *(__nv_bfloat162*)(Ch + (size_t)(row + 8) * DMODEL + col) = __halves2bfloat162(h0, h1);
            *(__nv_bfloat162*)(Cl + (size_t)(row + 8) * DMODEL + col) = __halves2bfloat162(l0, l1);
        }
    }
}

// ============================================================
// Kernel 2: scores. 128x128 tile, K=64 resident, 256 thr,
// warp 64x32. Pure uint4 copies of bf16 planes, no trans.
// ============================================================
#define P2 72  // (144B rows)

__global__ __launch_bounds__(256) void scores_kernel() {
    extern __shared__ __align__(16) __nv_bfloat16 sm2[];
    __nv_bfloat16* Qh = sm2;
    __nv_bfloat16* Ql = Qh + 128 * P2;
    __nv_bfloat16* Kh2 = Ql + 128 * P2;
    __nv_bfloat16* Kl2 = Kh2 + 128 * P2;

    const int bh = blockIdx.z;
    const int b = bh / NHEAD, h = bh % NHEAD;
    const int i0 = blockIdx.y * 128;
    const int j0 = blockIdx.x * 128;

    const int t = threadIdx.x, lane = t & 31, w = t >> 5;
    const int wm = (w & 1) * 64, wn = (w >> 1) * 32;

    const __nv_bfloat16* qhb = g_qh + (size_t)b * SEQ * DMODEL + h * DHEAD;
    const __nv_bfloat16* qlb = g_ql + (size_t)b * SEQ * DMODEL + h * DHEAD;
    const __nv_bfloat16* khb = g_kh + (size_t)b * SEQ * DMODEL + h * DHEAD;
    const __nv_bfloat16* klb = g_kl + (size_t)b * SEQ * DMODEL + h * DHEAD;

#pragma unroll
    for (int e = t; e < 1024; e += 256) {
        int r = e >> 3, c = (e & 7) * 8;
        *(uint4*)&Qh[r * P2 + c] = *(const uint4*)(qhb + (size_t)(i0 + r) * DMODEL + c);
        *(uint4*)&Ql[r * P2 + c] = *(const uint4*)(qlb + (size_t)(i0 + r) * DMODEL + c);
        *(uint4*)&Kh2[r * P2 + c] = *(const uint4*)(khb + (size_t)(j0 + r) * DMODEL + c);
        *(uint4*)&Kl2[r * P2 + c] = *(const uint4*)(klb + (size_t)(j0 + r) * DMODEL + c);
    }
    __syncthreads();

    float acc[4][4][4] = {};
    const int arow = wm + (lane & 15);
    const int bro = wn + (lane & 7) + (lane >> 4) * 8;

#pragma unroll
    for (int ks = 0; ks < 4; ks++) {
        const int acol = ks * 16 + (lane >> 4) * 8;
        const int bcol = ks * 16 + ((lane >> 3) & 1) * 8;
        uint32_t a[4][4], b[4][2];
        ldA<P2, 4>(Qh, arow, acol, a);
        ldB<P2, 2>(Kh2, bro, bcol, b);
        mma_tiles<4, 4>(acc, a, b);
        ldB<P2, 2>(Kl2, bro, bcol, b);
        mma_tiles<4, 4>(acc, a, b);
        ldA<P2, 4>(Ql, arow, acol, a);
        ldB<P2, 2>(Kh2, bro, bcol, b);
        mma_tiles<4, 4>(acc, a, b);
    }

    float* Sb = g_attn + (size_t)(b * NHEAD + h) * SEQ * SEQ;
    const int g = lane >> 2, tig = lane & 3;
#pragma unroll
    for (int mt = 0; mt < 4; mt++) {
        int row = i0 + wm + mt * 16 + g;
#pragma unroll
        for (int nt = 0; nt < 4; nt++) {
            int col = j0 + wn + nt * 8 + 2 * tig;
            *(float2*)(Sb + (size_t)row * SEQ + col) =
                make_float2(acc[mt][nt][0], acc[mt][nt][1]);
            *(float2*)(Sb + (size_t)(row + 8) * SEQ + col) =
                make_float2(acc[mt][nt][2], acc[mt][nt][3]);
        }
    }
}

// ============================================================
// Kernel 3: softmax + theta mix + LN; writes bf16 hi/lo planes.
// ============================================================
#define NW3 16

__device__ __forceinline__ void blockReduceMax12(float v[12], float* red) {
#pragma unroll
    for (int h = 0; h < 12; h++)
#pragma unroll
        for (int o = 16; o; o >>= 1)
            v[h] = fmaxf(v[h], __shfl_xor_sync(0xffffffffu, v[h], o));
    int w = threadIdx.x >> 5;
    if ((threadIdx.x & 31) == 0) {
#pragma unroll
        for (int h = 0; h < 12; h++) red[h * NW3 + w] = v[h];
    }
    __syncthreads();
#pragma unroll
    for (int h = 0; h < 12; h++) {
        float m = red[h * NW3];
#pragma unroll
        for (int w2 = 1; w2 < NW3; w2++) m = fmaxf(m, red[h * NW3 + w2]);
        v[h] = m;
    }
    __syncthreads();
}

__device__ __forceinline__ void blockReduceSum12(float v[12], float* red) {
#pragma unroll
    for (int h = 0; h < 12; h++)
#pragma unroll
        for (int o = 16; o; o >>= 1)
            v[h] += __shfl_xor_sync(0xffffffffu, v[h], o);
    int w = threadIdx.x >> 5;
    if ((threadIdx.x & 31) == 0) {
#pragma unroll
        for (int h = 0; h < 12; h++) red[h * NW3 + w] = v[h];
    }
    __syncthreads();
#pragma unroll
    for (int h = 0; h < 12; h++) {
        float m = red[h * NW3];
#pragma unroll
        for (int w2 = 1; w2 < NW3; w2++) m += red[h * NW3 + w2];
        v[h] = m;
    }
    __syncthreads();
}

__device__ __forceinline__ void blockReduceSum24(float v[24], float* red) {
#pragma unroll
    for (int h = 0; h < 24; h++)
#pragma unroll
        for (int o = 16; o; o >>= 1)
            v[h] += __shfl_xor_sync(0xffffffffu, v[h], o);
    int w = threadIdx.x >> 5;
    if ((threadIdx.x & 31) == 0) {
#pragma unroll
        for (int h = 0; h < 24; h++) red[h * NW3 + w] = v[h];
    }
    __syncthreads();
#pragma unroll
    for (int h = 0; h < 24; h++) {
        float m = red[h * NW3];
#pragma unroll
        for (int w2 = 1; w2 < NW3; w2++) m += red[h * NW3 + w2];
        v[h] = m;
    }
    __syncthreads();
}

__global__ __launch_bounds__(512) void softmax_theta_ln_kernel(
    const float* __restrict__ theta,
    const float* __restrict__ lnS,
    const float* __restrict__ lnB) {
    __shared__ float th[144];
    __shared__ float red[24 * NW3];

    const int bq = blockIdx.x;
    const int b = bq >> 10;
    const int qi = bq & 1023;
    const int t = threadIdx.x;  // owns k = 2t, 2t+1

    if (t < 144) th[t] = theta[t];

    float2 r[NHEAD];
#pragma unroll
    for (int h = 0; h < NHEAD; h++) {
        const float* src = g_attn + ((size_t)(b * NHEAD + h) * SEQ + qi) * SEQ;
        r[h] = *(const float2*)(src + 2 * t);
    }
    float2 s2v = *(const float2*)(lnS + 2 * t);
    float2 b2v = *(const float2*)(lnB + 2 * t);
    __syncthreads();

    float mx[NHEAD];
#pragma unroll
    for (int h = 0; h < NHEAD; h++) mx[h] = fmaxf(r[h].x, r[h].y);
    blockReduceMax12(mx, red);

    float sum[NHEAD];
#pragma unroll
    for (int h = 0; h < NHEAD; h++) {
        r[h].x = __expf(r[h].x - mx[h]);
        r[h].y = __expf(r[h].y - mx[h]);
        sum[h] = r[h].x + r[h].y;
    }
    blockReduceSum12(sum, red);
#pragma unroll
    for (int h = 0; h < NHEAD; h++) {
        float inv = 1.0f / sum[h];
        r[h].x *= inv;
        r[h].y *= inv;
    }

    float2 a[NHEAD];
#pragma unroll
    for (int i = 0; i < NHEAD; i++) {
        float ax = 0.f, ay = 0.f;
#pragma unroll
        for (int h = 0; h < NHEAD; h++) {
            float wv = th[h * NHEAD + i];
            ax += wv * r[h].x;
            ay += wv * r[h].y;
        }
        a[i].x = ax;
        a[i].y = ay;
    }

    float st[24];
#pragma unroll
    for (int i = 0; i < NHEAD; i++) {
        st[i] = a[i].x + a[i].y;
        st[12 + i] = a[i].x * a[i].x + a[i].y * a[i].y;
    }
    blockReduceSum24(st, red);

#pragma unroll
    for (int i = 0; i < NHEAD; i++) {
        float mean = st[i] * (1.0f / SEQ);
        float var = st[12 + i] * (1.0f / SEQ) - mean * mean;
        float rstd = rsqrtf(var + 1e-6f);
        size_t off = ((size_t)(b * NHEAD + i) * SEQ + qi) * SEQ + 2 * t;
        float ox = (a[i].x - mean) * rstd * s2v.x + b2v.x;
        float oy = (a[i].y - mean) * rstd * s2v.y + b2v.y;
        __nv_bfloat16 h0, l0, h1, l1;
        split2(ox, h0, l0);
        split2(oy, h1, l1);
        *(__nv_bfloat162*)(g_ah + off) = __halves2bfloat162(h0, h1);
        *(__nv_bfloat162*)(g_al + off) = __halves2bfloat162(l0, l1);
    }
}

// ============================================================
// Kernel 4: out[b,k,h,d] = sum_q A[b,h,q,k]*v[b,q,h,d].
// 128(k) x 64(d) tile, q-chunk 32, 256 thr, warp 32x32.
// Both operands via ldmatrix.trans; pure uint4 copies.
// ============================================================
#define PA 136  // attn [q][k] pitch (272B rows)
#define PV 72   // v [q][d] pitch (144B rows)

__global__ __launch_bounds__(256) void out_gemm_kernel(float* __restrict__ out) {
    const int bh = blockIdx.y;
    const int b = bh / NHEAD, h = bh % NHEAD;
    const int k0b = blockIdx.x * 128;

    __shared__ __align__(16) __nv_bfloat16 Ahs[32 * PA], Als[32 * PA];
    __shared__ __align__(16) __nv_bfloat16 Vhs[32 * PV], Vls[32 * PV];

    const int t = threadIdx.x, lane = t & 31, w = t >> 5;
    const int wm = (w & 3) * 32;   // k-dim
    const int wn = (w >> 2) * 32;  // d-dim

    const __nv_bfloat16* ahb = g_ah + (size_t)(b * NHEAD + h) * SEQ * SEQ;
    const __nv_bfloat16* alb = g_al + (size_t)(b * NHEAD + h) * SEQ * SEQ;
    const __nv_bfloat16* vhb = g_vh + (size_t)b * SEQ * DMODEL + h * DHEAD;
    const __nv_bfloat16* vlb = g_vl + (size_t)b * SEQ * DMODEL + h * DHEAD;

    float acc[2][4][4] = {};

    for (int q0 = 0; q0 < SEQ; q0 += 32) {
        // attn planes: [32 q][128 k]
#pragma unroll
        for (int i = 0; i < 2; i++) {
            int idx = t + i * 256;
            int r = idx >> 4, c = (idx & 15) * 8;
            *(uint4*)&Ahs[r * PA + c] =
                *(const uint4*)(ahb + (size_t)(q0 + r) * SEQ + k0b + c);
            *(uint4*)&Als[r * PA + c] =
                *(const uint4*)(alb + (size_t)(q0 + r) * SEQ + k0b + c);
        }
        // v planes: [32 q][64 d]
        {
            int r = t >> 3, c = (t & 7) * 8;
            *(uint4*)&Vhs[r * PV + c] =
                *(const uint4*)(vhb + (size_t)(q0 + r) * DMODEL + c);
            *(uint4*)&Vls[r * PV + c] =
                *(const uint4*)(vlb + (size_t)(q0 + r) * DMODEL + c);
        }
        __syncthreads();

#pragma unroll
        for (int ks = 0; ks < 2; ks++) {
            const int qc = ks * 16;
            uint32_t a[2][4], bfr[4][2];
            ldAT<PA, 2>(Ahs, qc, wm, lane, a);
            ldBT<PV, 2>(Vhs, qc, wn, lane, bfr);
            mma_tiles<2, 4>(acc, a, bfr);
            ldBT<PV, 2>(Vls, qc, wn, lane, bfr);
            mma_tiles<2, 4>(acc, a, bfr);
            ldAT<PA, 2>(Als, qc, wm, lane, a);
            ldBT<PV, 2>(Vhs, qc, wn, lane, bfr);
            mma_tiles<2, 4>(acc, a, bfr);
        }
        __syncthreads();
    }

    const int g = lane >> 2, tig = lane & 3;
#pragma unroll
    for (int mt = 0; mt < 2; mt++) {
        int row = k0b + wm + mt * 16 + g;
#pragma unroll
        for (int nt = 0; nt < 4; nt++) {
            int col = h * DHEAD + wn + nt * 8 + 2 * tig;
            *(float2*)(out + (size_t)(b * SEQ + row) * DMODEL + col) =
                make_float2(acc[mt][nt][0], acc[mt][nt][1]);
            *(float2*)(out + (size_t)(b * SEQ + row + 8) * DMODEL + col) =
                make_float2(acc[mt][nt][2], acc[mt][nt][3]);
        }
    }
}

// ============================================================
extern "C" void kernel_launch(void* const* d_in, const int* in_sizes, int n_in,
                              void* d_out, int out_size) {
    const float* x     = (const float*)d_in[0];
    const float* Wq    = (const float*)d_in[1];
    const float* Wk    = (const float*)d_in[2];
    const float* Wv    = (const float*)d_in[3];
    const float* theta = (const float*)d_in[4];
    const float* lnS   = (const float*)d_in[5];
    const float* lnB   = (const float*)d_in[6];
    float* out = (float*)d_out;

    // 1. QKV projections -> bf16 hi/lo planes
    {
        dim3 grid(DMODEL / 128, BN / 128, 3);
        qkv_gemm_kernel<<<grid, 256>>>(x, Wq, Wk, Wv);
    }
    // 2. attention scores (fp32 out)
    {
        int smem = 4 * 128 * P2 * sizeof(__nv_bfloat16);  // 73728 B
        cudaFuncSetAttribute(scores_kernel,
                             cudaFuncAttributeMaxDynamicSharedMemorySize, smem);
        dim3 grid(SEQ / 128, SEQ / 128, BATCH * NHEAD);
        scores_kernel<<<grid, 256, smem>>>();
    }
    // 3. fused softmax + theta mix + LayerNorm -> bf16 hi/lo planes
    {
        softmax_theta_ln_kernel<<<BATCH * SEQ, 512>>>(theta, lnS, lnB);
    }
    // 4. output GEMM (A^T V, both operands via ldmatrix.trans)
    {
        dim3 grid(SEQ / 128, BATCH * NHEAD);
        out_gemm_kernel<<<grid, 256>>>(out);
    }
}